// round 1
// baseline (speedup 1.0000x reference)
#include <cuda_runtime.h>
#include <cstdint>

// Problem constants (fixed shapes from the dataset)
#define DK    4096      // contraction dim == x last dim
#define NCOL  64        // output cols (rank / in_features)
#define TM    128       // rows per block in the big GEMM
#define TK    32        // k-slice per pipeline stage
#define MAX_M 16384     // B*S

// -------- scratch (no allocations allowed) --------
__device__ float        g_W[DK * NCOL];        // (B@A) * 0.25 * mask  [4096,64]
__device__ float        g_Y[MAX_M * NCOL];     // pre-quant GEMM result
__device__ float        g_colscale[NCOL];
__device__ unsigned int g_absmax_bits;

// -------- helpers --------
__device__ __forceinline__ unsigned long long ffma2(unsigned long long a,
                                                    unsigned long long b,
                                                    unsigned long long c) {
    unsigned long long d;
    asm("fma.rn.f32x2 %0, %1, %2, %3;" : "=l"(d) : "l"(a), "l"(b), "l"(c));
    return d;
}
__device__ __forceinline__ unsigned long long fadd2(unsigned long long a,
                                                    unsigned long long b) {
    unsigned long long d;
    asm("add.rn.f32x2 %0, %1, %2;" : "=l"(d) : "l"(a), "l"(b));
    return d;
}
__device__ __forceinline__ unsigned long long pack2(float lo, float hi) {
    unsigned long long r;
    asm("mov.b64 %0, {%1, %2};" : "=l"(r) : "f"(lo), "f"(hi));
    return r;
}
__device__ __forceinline__ float lo2(unsigned long long v) {
    return __uint_as_float((unsigned)(v & 0xFFFFFFFFull));
}
__device__ __forceinline__ float hi2(unsigned long long v) {
    return __uint_as_float((unsigned)(v >> 32));
}
__device__ __forceinline__ void cp_async16(uint32_t saddr, const void* g) {
    asm volatile("cp.async.cg.shared.global [%0], [%1], 16;" :: "r"(saddr), "l"(g));
}
__device__ __forceinline__ void cp_commit() {
    asm volatile("cp.async.commit_group;");
}
__device__ __forceinline__ void cp_wait0() {
    asm volatile("cp.async.wait_group 0;");
}

// -------- kernel 0: rank mask + scaling, zero absmax --------
__global__ void k_prep(const float* __restrict__ ri) {
    __shared__ int cnt;
    int j = threadIdx.x;  // 64 threads
    if (j == 0) { cnt = 0; g_absmax_bits = 0u; }
    __syncthreads();
    float s = 1.0f / (1.0f + expf(-ri[j]));
    int a = (s > 0.1f) ? 1 : 0;
    atomicAdd(&cnt, a);
    __syncthreads();
    float f = (cnt > 0) ? (float)a : 1.0f;
    g_colscale[j] = 0.25f * f;   // SCALING = ALPHA/RANK = 0.25, mask folded in
}

// -------- kernel 1: W = (lora_B @ lora_A) * colscale --------
// grid = DK/4 blocks, block = (64, 4)
__global__ void k_w(const float* __restrict__ Bm, const float* __restrict__ A) {
    __shared__ float sA[64 * 64];
    __shared__ float sB[4 * 64];
    int tx = threadIdx.x;               // 0..63 -> j (output col)
    int ty = threadIdx.y;               // 0..3  -> row within block
    int tid = ty * 64 + tx;             // 0..255
    int i = blockIdx.x * 4 + ty;        // W row
#pragma unroll
    for (int t = 0; t < 16; t++) sA[tid + t * 256] = A[tid + t * 256];
    sB[tid] = Bm[blockIdx.x * 256 + tid];
    __syncthreads();
    float acc = 0.0f;
#pragma unroll 8
    for (int r = 0; r < 64; r++)
        acc = fmaf(sB[ty * 64 + r], sA[r * 64 + tx], acc);
    g_W[i * NCOL + tx] = acc * g_colscale[tx];
}

// -------- kernel 2: Y = x @ W  (fp32, packed f32x2 FMA, cp.async pipeline) --------
// grid = M/TM, block = 256.  Thread (tx=tid&15, ty=tid>>4) owns rows ty*8..+7,
// cols tx*4..+3, packed as c[pair p][col j] = f32x2 over rows (2p, 2p+1).
__global__ void __launch_bounds__(256, 1) k_gemm(const float* __restrict__ x) {
    extern __shared__ float smem[];
    float* sx = smem;                      // [2][TM][TK]   32 KB
    float* sw = smem + 2 * TM * TK;        // [2][TK][NCOL] 16 KB
    uint32_t sx_u = (uint32_t)__cvta_generic_to_shared(sx);
    uint32_t sw_u = (uint32_t)__cvta_generic_to_shared(sw);

    int tid = threadIdx.x;
    int tx = tid & 15;
    int ty = tid >> 4;
    int m0 = blockIdx.x * TM;
    const float* xblk = x + (size_t)m0 * DK;

    // prefetch address decomposition
    int xrow = tid >> 3;            // + i*32 (i=0..3): 128 rows x 2 quads
    int xkq  = (tid & 7) * 4;       // float offset within k-slice
    int wkr  = tid >> 4;            // + i*16 (i=0..1)
    int wcq  = (tid & 15) * 4;

    unsigned long long c[4][4];
#pragma unroll
    for (int p = 0; p < 4; p++)
#pragma unroll
        for (int j = 0; j < 4; j++) c[p][j] = 0ull;

    // prefetch tile 0 into buffer 0
#pragma unroll
    for (int i = 0; i < 4; i++) {
        int row = xrow + i * 32;
        cp_async16(sx_u + (uint32_t)((row * TK + xkq) * 4),
                   xblk + (size_t)row * DK + xkq);
    }
#pragma unroll
    for (int i = 0; i < 2; i++) {
        int kr = wkr + i * 16;
        cp_async16(sw_u + (uint32_t)((kr * NCOL + wcq) * 4),
                   &g_W[kr * NCOL + wcq]);
    }
    cp_commit();

    const int NIT = DK / TK;   // 128
    for (int it = 0; it < NIT; it++) {
        cp_wait0();
        __syncthreads();
        if (it + 1 < NIT) {
            int k0 = (it + 1) * TK;
            uint32_t bx = ((it + 1) & 1) ? (uint32_t)(TM * TK * 4) : 0u;
            uint32_t bw = ((it + 1) & 1) ? (uint32_t)(TK * NCOL * 4) : 0u;
#pragma unroll
            for (int i = 0; i < 4; i++) {
                int row = xrow + i * 32;
                cp_async16(sx_u + bx + (uint32_t)((row * TK + xkq) * 4),
                           xblk + (size_t)row * DK + k0 + xkq);
            }
#pragma unroll
            for (int i = 0; i < 2; i++) {
                int kr = wkr + i * 16;
                cp_async16(sw_u + bw + (uint32_t)((kr * NCOL + wcq) * 4),
                           &g_W[(k0 + kr) * NCOL + wcq]);
            }
            cp_commit();
        }

        const float* cx = sx + (it & 1) * (TM * TK);
        const float* cw = sw + (it & 1) * (TK * NCOL);

        // per-tile partial accumulators (blocked summation: shortens the
        // fp32 error chain from 4096 to 128+32 ~ matches jax fp32 closely)
        unsigned long long t[4][4];
#pragma unroll
        for (int p = 0; p < 4; p++)
#pragma unroll
            for (int j = 0; j < 4; j++) t[p][j] = 0ull;

#pragma unroll 8
        for (int kk = 0; kk < TK; kk++) {
            float4 b = *(const float4*)&cw[kk * NCOL + tx * 4];
            float a0 = cx[(ty * 8 + 0) * TK + kk];
            float a1 = cx[(ty * 8 + 1) * TK + kk];
            float a2 = cx[(ty * 8 + 2) * TK + kk];
            float a3 = cx[(ty * 8 + 3) * TK + kk];
            float a4 = cx[(ty * 8 + 4) * TK + kk];
            float a5 = cx[(ty * 8 + 5) * TK + kk];
            float a6 = cx[(ty * 8 + 6) * TK + kk];
            float a7 = cx[(ty * 8 + 7) * TK + kk];
            unsigned long long ap0 = pack2(a0, a1);
            unsigned long long ap1 = pack2(a2, a3);
            unsigned long long ap2 = pack2(a4, a5);
            unsigned long long ap3 = pack2(a6, a7);
            unsigned long long bd0 = pack2(b.x, b.x);
            unsigned long long bd1 = pack2(b.y, b.y);
            unsigned long long bd2 = pack2(b.z, b.z);
            unsigned long long bd3 = pack2(b.w, b.w);
            t[0][0] = ffma2(ap0, bd0, t[0][0]);
            t[0][1] = ffma2(ap0, bd1, t[0][1]);
            t[0][2] = ffma2(ap0, bd2, t[0][2]);
            t[0][3] = ffma2(ap0, bd3, t[0][3]);
            t[1][0] = ffma2(ap1, bd0, t[1][0]);
            t[1][1] = ffma2(ap1, bd1, t[1][1]);
            t[1][2] = ffma2(ap1, bd2, t[1][2]);
            t[1][3] = ffma2(ap1, bd3, t[1][3]);
            t[2][0] = ffma2(ap2, bd0, t[2][0]);
            t[2][1] = ffma2(ap2, bd1, t[2][1]);
            t[2][2] = ffma2(ap2, bd2, t[2][2]);
            t[2][3] = ffma2(ap2, bd3, t[2][3]);
            t[3][0] = ffma2(ap3, bd0, t[3][0]);
            t[3][1] = ffma2(ap3, bd1, t[3][1]);
            t[3][2] = ffma2(ap3, bd2, t[3][2]);
            t[3][3] = ffma2(ap3, bd3, t[3][3]);
        }
#pragma unroll
        for (int p = 0; p < 4; p++)
#pragma unroll
            for (int j = 0; j < 4; j++) c[p][j] = fadd2(c[p][j], t[p][j]);
    }

    // epilogue: write Y, reduce abs-max
    float tmax = 0.0f;
#pragma unroll
    for (int p = 0; p < 4; p++) {
        int r = m0 + ty * 8 + 2 * p;
        float4 v0 = make_float4(lo2(c[p][0]), lo2(c[p][1]), lo2(c[p][2]), lo2(c[p][3]));
        float4 v1 = make_float4(hi2(c[p][0]), hi2(c[p][1]), hi2(c[p][2]), hi2(c[p][3]));
        *(float4*)&g_Y[(size_t)r * NCOL + tx * 4] = v0;
        *(float4*)&g_Y[(size_t)(r + 1) * NCOL + tx * 4] = v1;
        tmax = fmaxf(tmax, fmaxf(fmaxf(fabsf(v0.x), fabsf(v0.y)),
                                 fmaxf(fabsf(v0.z), fabsf(v0.w))));
        tmax = fmaxf(tmax, fmaxf(fmaxf(fabsf(v1.x), fabsf(v1.y)),
                                 fmaxf(fabsf(v1.z), fabsf(v1.w))));
    }
#pragma unroll
    for (int off = 16; off; off >>= 1)
        tmax = fmaxf(tmax, __shfl_xor_sync(0xffffffffu, tmax, off));
    if ((tid & 31) == 0)
        atomicMax(&g_absmax_bits, __float_as_uint(tmax));  // |v| >= 0: uint order == float order
}

// -------- kernel 3: NF4 quantize --------
__device__ __forceinline__ float nf4_nearest(float v) {
    const float L[16] = {
        -1.0f, -0.6961928009986877f, -0.5250730514526367f, -0.39491748809814453f,
        -0.28444138169288635f, -0.18477343022823334f, -0.09105003625154495f, 0.0f,
        0.07958029955625534f, 0.16093020141124725f, 0.24611230194568634f,
        0.33791524171829224f, 0.44070982933044434f, 0.5626170039176941f,
        0.7229568362236023f, 1.0f };
    float bestd = fabsf(v - L[0]);
    float lev = L[0];
#pragma unroll
    for (int i = 1; i < 16; i++) {
        float d = fabsf(v - L[i]);
        if (d < bestd) { bestd = d; lev = L[i]; }   // strict < keeps first index (argmin tie rule)
    }
    return lev;
}

__global__ void k_quant(float* __restrict__ out, const float* __restrict__ qs, int n4) {
    int i = blockIdx.x * blockDim.x + threadIdx.x;
    if (i >= n4) return;
    float absmax = __uint_as_float(g_absmax_bits);
    float qscale = qs[0];
    float4 y = ((const float4*)g_Y)[i];
    float4 o;
    if (absmax > 0.0f) {
        o.x = nf4_nearest(y.x / absmax) * absmax;
        o.y = nf4_nearest(y.y / absmax) * absmax;
        o.z = nf4_nearest(y.z / absmax) * absmax;
        o.w = nf4_nearest(y.w / absmax) * absmax;
    } else {
        o = y;
    }
    o.x *= qscale; o.y *= qscale; o.z *= qscale; o.w *= qscale;
    ((float4*)out)[i] = o;
}

// -------- launch --------
extern "C" void kernel_launch(void* const* d_in, const int* in_sizes, int n_in,
                              void* d_out, int out_size) {
    const float* x  = (const float*)d_in[0];   // [B,S,4096]
    const float* A  = (const float*)d_in[1];   // [64,64]
    const float* Bm = (const float*)d_in[2];   // [4096,64]
    const float* qs = (const float*)d_in[3];   // [1]
    const float* ri = (const float*)d_in[4];   // [64]
    float* out = (float*)d_out;

    int M = in_sizes[0] / DK;                  // 16384
    int smem_bytes = (2 * TM * TK + 2 * TK * NCOL) * 4;   // 49152

    cudaFuncSetAttribute(k_gemm, cudaFuncAttributeMaxDynamicSharedMemorySize, smem_bytes);

    k_prep<<<1, 64>>>(ri);
    k_w<<<DK / 4, dim3(64, 4)>>>(Bm, A);
    k_gemm<<<M / TM, 256, smem_bytes>>>(x);
    int n4 = (M * NCOL) / 4;
    k_quant<<<(n4 + 255) / 256, 256>>>(out, qs, n4);
}

// round 3
// speedup vs baseline: 1.5529x; 1.5529x over previous
#include <cuda_runtime.h>
#include <cstdint>

#define DK    4096
#define NCOL  64
#define TM    128
#define KC    32
#define NIT   128            // DK / KC
#define MAX_M 16384

// ---------------- device scratch ----------------
// W in mma B-fragment layout: [k8 512][term 2][lane 32][20 floats (16 used, 4 pad)]
__device__ float        g_Wf[512 * 2 * 32 * 20];
__device__ float        g_Y[MAX_M * NCOL];
__device__ float        g_colscale[NCOL];
__device__ unsigned int g_absmax_bits;

// ---------------- helpers ----------------
__device__ __forceinline__ uint32_t tf32_rna(float f) {
    uint32_t r;
    asm("cvt.rna.tf32.f32 %0, %1;" : "=r"(r) : "f"(f));
    return r;
}
__device__ __forceinline__ float asf(uint32_t u) { return __uint_as_float(u); }

__device__ __forceinline__ void cp_async16(uint32_t dst, const void* src) {
    asm volatile("cp.async.cg.shared.global [%0], [%1], 16;" :: "r"(dst), "l"(src));
}
#define CP_COMMIT() asm volatile("cp.async.commit_group;")
#define CP_WAIT0()  asm volatile("cp.async.wait_group 0;")

__device__ __forceinline__ void lds128(uint4& v, uint32_t a) {
    asm volatile("ld.shared.v4.b32 {%0,%1,%2,%3}, [%4];"
                 : "=r"(v.x), "=r"(v.y), "=r"(v.z), "=r"(v.w) : "r"(a));
}
__device__ __forceinline__ float lds32f(uint32_t a) {
    float f;
    asm volatile("ld.shared.f32 %0, [%1];" : "=f"(f) : "r"(a));
    return f;
}

// m16n8k8 tf32 mma, D += A*B (accumulate in place)
__device__ __forceinline__ void mma8(float4& d, uint32_t a0, uint32_t a1,
                                     uint32_t a2, uint32_t a3,
                                     uint32_t b0, uint32_t b1) {
    asm volatile(
        "mma.sync.aligned.m16n8k8.row.col.f32.tf32.tf32.f32 "
        "{%0,%1,%2,%3},{%4,%5,%6,%7},{%8,%9},{%0,%1,%2,%3};"
        : "+f"(d.x), "+f"(d.y), "+f"(d.z), "+f"(d.w)
        : "r"(a0), "r"(a1), "r"(a2), "r"(a3), "r"(b0), "r"(b1));
}

// ---------------- kernel 0: rank mask + scaling ----------------
__global__ void k_prep(const float* __restrict__ ri) {
    __shared__ int cnt;
    int j = threadIdx.x;
    if (j == 0) { cnt = 0; g_absmax_bits = 0u; }
    __syncthreads();
    float s = 1.0f / (1.0f + expf(-ri[j]));
    int a = (s > 0.1f) ? 1 : 0;
    atomicAdd(&cnt, a);
    __syncthreads();
    float f = (cnt > 0) ? (float)a : 1.0f;
    g_colscale[j] = 0.25f * f;     // SCALING=0.25, mask folded
}

// ---------------- kernel 1: W = (B@A)*colscale -> split -> fragment layout ----
// grid = DK/4, block = (64,4). Value W[k][n] lands in b0 (k%8<4) or b1 slot.
__global__ void k_w(const float* __restrict__ Bm, const float* __restrict__ A) {
    __shared__ float sA[64 * 64];
    __shared__ float sB[4 * 64];
    int tx = threadIdx.x, ty = threadIdx.y;
    int tid = ty * 64 + tx;
    int k = blockIdx.x * 4 + ty;           // W row (0..4095)
#pragma unroll
    for (int t = 0; t < 16; t++) sA[tid + t * 256] = A[tid + t * 256];
    sB[tid] = Bm[blockIdx.x * 256 + tid];
    __syncthreads();
    float acc = 0.0f;
#pragma unroll 8
    for (int r = 0; r < 64; r++)
        acc = fmaf(sB[ty * 64 + r], sA[r * 64 + tx], acc);
    float w = acc * g_colscale[tx];

    uint32_t h = tf32_rna(w);
    float lof = w - asf(h);
    uint32_t lb = tf32_rna(lof);

    int n = tx;
    int k8 = k >> 3, kr = k & 7;
    int lane = ((n & 7) << 2) | (kr & 3);
    int f = ((n >> 3) << 1) | (kr >> 2);       // [tile][b0/b1] interleaved
    size_t base = ((size_t)(k8 * 2) * 32 + lane) * 20 + f;
    g_Wf[base]       = asf(h);                 // term 0 (hi)
    g_Wf[base + 640] = asf(lb);                // term 1 (lo): +32*20
}

// ---------------- kernel 2: Y = x @ W via mma.sync 3xTF32 ----------------
// grid = M/128, block = 128 (4 warps). Warp (mh=wid>>1, nh=wid&1) owns
// rows mh*64..+63 (4 m16 tiles) x cols nh*32..+31 (4 n8 tiles).
#define SMA_SZ 18432                 // 128 rows * 144B (stride 36 floats)
#define SMB_SZ 20480                 // 4 k8 * 2 term * 32 lane * 80B
#define SM_TOTAL (2 * SMA_SZ + 2 * SMB_SZ)

__global__ void __launch_bounds__(128, 1) k_gemm(const float* __restrict__ x) {
    extern __shared__ char smem[];
    uint32_t sbA = (uint32_t)__cvta_generic_to_shared(smem);
    uint32_t sbB = sbA + 2 * SMA_SZ;

    int tid = threadIdx.x;
    int wid = tid >> 5, l = tid & 31;
    int mh = wid >> 1, nh = wid & 1;
    int m0 = blockIdx.x * TM;
    const float* xblk = x + (size_t)m0 * DK;
    const char* wsrc = (const char*)g_Wf;

    float4 C[4][4], S[4][4];
#pragma unroll
    for (int a = 0; a < 4; a++)
#pragma unroll
        for (int b = 0; b < 4; b++) {
            C[a][b] = make_float4(0.f, 0.f, 0.f, 0.f);
            S[a][b] = make_float4(0.f, 0.f, 0.f, 0.f);
        }

    int r_in = l >> 2;      // 0..7
    int cq   = l & 3;       // 0..3

    // ---- prologue: cp chunk 0 into buffer 0
#pragma unroll
    for (int i = 0; i < 8; i++) {
        int idx = i * 128 + tid;
        int row = idx >> 3, q = idx & 7;
        cp_async16(sbA + (uint32_t)(row * 144 + q * 16),
                   xblk + (size_t)row * DK + q * 4);
    }
#pragma unroll
    for (int i = 0; i < 10; i++) {
        int idx = i * 128 + tid;
        cp_async16(sbB + (uint32_t)(idx * 16), wsrc + (size_t)idx * 16);
    }
    CP_COMMIT();

#pragma unroll 1
    for (int c = 0; c < NIT; c++) {
        int buf = c & 1;
        CP_WAIT0();
        __syncthreads();

        if (c + 1 < NIT) {
            int nb = (c + 1) & 1;
            int k0 = (c + 1) * KC;
            uint32_t aoff = sbA + (uint32_t)(nb * SMA_SZ);
            uint32_t boff = sbB + (uint32_t)(nb * SMB_SZ);
            const char* bs = wsrc + (size_t)(c + 1) * SMB_SZ;
#pragma unroll
            for (int i = 0; i < 8; i++) {
                int idx = i * 128 + tid;
                int row = idx >> 3, q = idx & 7;
                cp_async16(aoff + (uint32_t)(row * 144 + q * 16),
                           xblk + (size_t)row * DK + k0 + q * 4);
            }
#pragma unroll
            for (int i = 0; i < 10; i++) {
                int idx = i * 128 + tid;
                cp_async16(boff + (uint32_t)(idx * 16), bs + (size_t)idx * 16);
            }
            CP_COMMIT();
        }

        uint32_t ab = sbA + (uint32_t)(buf * SMA_SZ);
        uint32_t bb = sbB + (uint32_t)(buf * SMB_SZ);

#pragma unroll
        for (int s = 0; s < 4; s++) {
            // B fragments: [t0 b0][t0 b1][t1 b0][t1 b1]... per lds.128
            uint4 BH0, BH1, BL0, BL1;
            uint32_t bh = bb + (uint32_t)(((s * 2 + 0) * 32 + l) * 80 + nh * 32);
            uint32_t bl = bb + (uint32_t)(((s * 2 + 1) * 32 + l) * 80 + nh * 32);
            lds128(BH0, bh); lds128(BH1, bh + 16);
            lds128(BL0, bl); lds128(BL1, bl + 16);

#pragma unroll
            for (int rt = 0; rt < 4; rt++) {
                uint32_t ra = ab + (uint32_t)((mh * 64 + rt * 16 + r_in) * 144
                                              + (s * 8 + cq) * 4);
                float a0 = lds32f(ra);
                float a2 = lds32f(ra + 16);
                float a1 = lds32f(ra + 8 * 144);
                float a3 = lds32f(ra + 8 * 144 + 16);

                uint32_t h0 = tf32_rna(a0), h1 = tf32_rna(a1);
                uint32_t h2 = tf32_rna(a2), h3 = tf32_rna(a3);
                uint32_t l0 = tf32_rna(a0 - asf(h0));
                uint32_t l1 = tf32_rna(a1 - asf(h1));
                uint32_t l2 = tf32_rna(a2 - asf(h2));
                uint32_t l3 = tf32_rna(a3 - asf(h3));

                mma8(C[rt][0], h0, h1, h2, h3, BH0.x, BH0.y);
                mma8(C[rt][0], h0, h1, h2, h3, BL0.x, BL0.y);
                mma8(C[rt][0], l0, l1, l2, l3, BH0.x, BH0.y);

                mma8(C[rt][1], h0, h1, h2, h3, BH0.z, BH0.w);
                mma8(C[rt][1], h0, h1, h2, h3, BL0.z, BL0.w);
                mma8(C[rt][1], l0, l1, l2, l3, BH0.z, BH0.w);

                mma8(C[rt][2], h0, h1, h2, h3, BH1.x, BH1.y);
                mma8(C[rt][2], h0, h1, h2, h3, BL1.x, BL1.y);
                mma8(C[rt][2], l0, l1, l2, l3, BH1.x, BH1.y);

                mma8(C[rt][3], h0, h1, h2, h3, BH1.z, BH1.w);
                mma8(C[rt][3], h0, h1, h2, h3, BL1.z, BL1.w);
                mma8(C[rt][3], l0, l1, l2, l3, BH1.z, BH1.w);
            }
        }

        // drain accumulators every 16 chunks (shortens fp32 error chain)
        if ((c & 15) == 15) {
#pragma unroll
            for (int a = 0; a < 4; a++)
#pragma unroll
                for (int b = 0; b < 4; b++) {
                    S[a][b].x += C[a][b].x; S[a][b].y += C[a][b].y;
                    S[a][b].z += C[a][b].z; S[a][b].w += C[a][b].w;
                    C[a][b] = make_float4(0.f, 0.f, 0.f, 0.f);
                }
        }
    }

    // ---- epilogue: store Y, reduce abs-max
    float mx = 0.0f;
#pragma unroll
    for (int rt = 0; rt < 4; rt++)
#pragma unroll
        for (int nt = 0; nt < 4; nt++) {
            float4 v = S[rt][nt];
            int row = m0 + mh * 64 + rt * 16 + r_in;
            int col = nh * 32 + nt * 8 + cq * 2;
            *(float2*)&g_Y[(size_t)row * NCOL + col]       = make_float2(v.x, v.y);
            *(float2*)&g_Y[(size_t)(row + 8) * NCOL + col] = make_float2(v.z, v.w);
            mx = fmaxf(mx, fmaxf(fmaxf(fabsf(v.x), fabsf(v.y)),
                                 fmaxf(fabsf(v.z), fabsf(v.w))));
        }
#pragma unroll
    for (int off = 16; off; off >>= 1)
        mx = fmaxf(mx, __shfl_xor_sync(0xffffffffu, mx, off));
    if (l == 0) atomicMax(&g_absmax_bits, __float_as_uint(mx));
}

// ---------------- kernel 3: NF4 quantize (midpoint count) ----------------
__global__ void k_quant(float* __restrict__ out, const float* __restrict__ qs, int n4) {
    const float L[16] = {
        -1.0f, -0.6961928009986877f, -0.5250730514526367f, -0.39491748809814453f,
        -0.28444138169288635f, -0.18477343022823334f, -0.09105003625154495f, 0.0f,
        0.07958029955625534f, 0.16093020141124725f, 0.24611230194568634f,
        0.33791524171829224f, 0.44070982933044434f, 0.5626170039176941f,
        0.7229568362236023f, 1.0f };
    float MID[15];
#pragma unroll
    for (int i = 0; i < 15; i++) MID[i] = 0.5f * (L[i] + L[i + 1]);

    int i = blockIdx.x * blockDim.x + threadIdx.x;
    if (i >= n4) return;
    float absmax = __uint_as_float(g_absmax_bits);
    float qscale = qs[0];
    float4 y = ((const float4*)g_Y)[i];
    float4 o;
    if (absmax > 0.0f) {
        float inv = 1.0f / absmax;
        float v[4] = { y.x * inv, y.y * inv, y.z * inv, y.w * inv };
        float r[4];
#pragma unroll
        for (int t = 0; t < 4; t++) {
            int idx = 0;
#pragma unroll
            for (int b = 0; b < 15; b++) idx += (v[t] > MID[b]) ? 1 : 0;
            r[t] = L[idx] * absmax;
        }
        o = make_float4(r[0], r[1], r[2], r[3]);
    } else {
        o = y;
    }
    o.x *= qscale; o.y *= qscale; o.z *= qscale; o.w *= qscale;
    ((float4*)out)[i] = o;
}

// ---------------- launch ----------------
extern "C" void kernel_launch(void* const* d_in, const int* in_sizes, int n_in,
                              void* d_out, int out_size) {
    const float* x  = (const float*)d_in[0];   // [4,4096,4096]
    const float* A  = (const float*)d_in[1];   // [64,64]
    const float* Bm = (const float*)d_in[2];   // [4096,64]
    const float* qs = (const float*)d_in[3];   // [1]
    const float* ri = (const float*)d_in[4];   // [64]
    float* out = (float*)d_out;

    int M = in_sizes[0] / DK;   // 16384

    cudaFuncSetAttribute(k_gemm, cudaFuncAttributeMaxDynamicSharedMemorySize, SM_TOTAL);

    k_prep<<<1, 64>>>(ri);
    k_w<<<DK / 4, dim3(64, 4)>>>(Bm, A);
    k_gemm<<<M / TM, 128, SM_TOTAL>>>(x);
    int n4 = (M * NCOL) / 4;
    k_quant<<<(n4 + 255) / 256, 256>>>(out, qs, n4);
}

// round 4
// speedup vs baseline: 2.0958x; 1.3496x over previous
#include <cuda_runtime.h>
#include <cuda_fp16.h>
#include <cstdint>

#define DK    4096
#define NCOL  64
#define TM    128
#define KC    32
#define NIT   128            // DK / KC
#define MAX_M 16384
#define WSC   4096.0f        // 2^12 W pre-scale (exact inverse in epilogue)
#define WSCI  (1.0f / 4096.0f)

// ---------------- device scratch ----------------
// W hi/lo fp16 in m16n8k16 B-fragment layout:
// [k16:256][term:2][grp:4][lane:32][8 u16]  (grp = n>>4; within lane 16B:
//  b32 idx = ntp*2+reg, half = kr&1;  ntp=(n>>3)&1, reg=kr>>3)
__device__ uint16_t     g_Whf[256 * 2 * 4 * 32 * 8];
__device__ float        g_Y[MAX_M * NCOL];
__device__ float        g_colscale[NCOL];
__device__ unsigned int g_absmax_bits;

// ---------------- helpers ----------------
__device__ __forceinline__ void cp_async16(uint32_t dst, const void* src) {
    asm volatile("cp.async.cg.shared.global [%0], [%1], 16;" :: "r"(dst), "l"(src));
}
#define CP_COMMIT() asm volatile("cp.async.commit_group;")
#define CP_WAIT0()  asm volatile("cp.async.wait_group 0;")

__device__ __forceinline__ void lds128(uint4& v, uint32_t a) {
    asm volatile("ld.shared.v4.b32 {%0,%1,%2,%3}, [%4];"
                 : "=r"(v.x), "=r"(v.y), "=r"(v.z), "=r"(v.w) : "r"(a));
}
__device__ __forceinline__ float2 lds64f(uint32_t a) {
    float2 v;
    asm volatile("ld.shared.v2.f32 {%0,%1}, [%2];" : "=f"(v.x), "=f"(v.y) : "r"(a));
    return v;
}

// pack two f32 -> fp16x2 (lo half = a, hi half = b)
__device__ __forceinline__ uint32_t f16x2_rn(float a, float b) {
    uint32_t r;
    asm("cvt.rn.f16x2.f32 %0, %1, %2;" : "=r"(r) : "f"(b), "f"(a));
    return r;
}
// unpack fp16x2 -> two f32
__device__ __forceinline__ void f16x2_unpack(uint32_t p, float& lo, float& hi) {
    asm("{.reg .f16 l, h; mov.b32 {l, h}, %2;"
        " cvt.f32.f16 %0, l; cvt.f32.f16 %1, h;}"
        : "=f"(lo), "=f"(hi) : "r"(p));
}
// split a pair of f32 into hi fp16x2 + lo fp16x2
__device__ __forceinline__ void split_pair(float2 x, uint32_t& h, uint32_t& l) {
    h = f16x2_rn(x.x, x.y);
    float hx, hy;
    f16x2_unpack(h, hx, hy);
    l = f16x2_rn(x.x - hx, x.y - hy);
}

// m16n8k16 fp16 mma, fp32 accumulate in place
__device__ __forceinline__ void mma16(float4& d, uint32_t a0, uint32_t a1,
                                      uint32_t a2, uint32_t a3,
                                      uint32_t b0, uint32_t b1) {
    asm volatile(
        "mma.sync.aligned.m16n8k16.row.col.f32.f16.f16.f32 "
        "{%0,%1,%2,%3},{%4,%5,%6,%7},{%8,%9},{%0,%1,%2,%3};"
        : "+f"(d.x), "+f"(d.y), "+f"(d.z), "+f"(d.w)
        : "r"(a0), "r"(a1), "r"(a2), "r"(a3), "r"(b0), "r"(b1));
}

// ---------------- kernel 0: rank mask + scaling ----------------
__global__ void k_prep(const float* __restrict__ ri) {
    __shared__ int cnt;
    int j = threadIdx.x;
    if (j == 0) { cnt = 0; g_absmax_bits = 0u; }
    __syncthreads();
    float s = 1.0f / (1.0f + expf(-ri[j]));
    int a = (s > 0.1f) ? 1 : 0;
    atomicAdd(&cnt, a);
    __syncthreads();
    float f = (cnt > 0) ? (float)a : 1.0f;
    g_colscale[j] = 0.25f * WSC * f;        // SCALING * 2^12 * mask
}

// ---------------- kernel 1: W=(B@A)*colscale -> fp16 hi/lo fragment layout ----
__global__ void k_w(const float* __restrict__ Bm, const float* __restrict__ A) {
    __shared__ float sA[64 * 64];
    __shared__ float sB[4 * 64];
    int tx = threadIdx.x, ty = threadIdx.y;
    int tid = ty * 64 + tx;
    int k = blockIdx.x * 4 + ty;            // 0..4095
#pragma unroll
    for (int t = 0; t < 16; t++) sA[tid + t * 256] = A[tid + t * 256];
    sB[tid] = Bm[blockIdx.x * 256 + tid];
    __syncthreads();
    float acc = 0.0f;
#pragma unroll 8
    for (int r = 0; r < 64; r++)
        acc = fmaf(sB[ty * 64 + r], sA[r * 64 + tx], acc);
    float w = acc * g_colscale[tx];

    __half hh = __float2half_rn(w);
    float  hf = __half2float(hh);
    __half hl = __float2half_rn(w - hf);

    int n = tx;
    int k16 = k >> 4, kr = k & 15;
    int reg = kr >> 3;
    int l   = ((n & 7) << 2) | ((kr & 7) >> 1);
    int grp = n >> 4;
    int ntp = (n >> 3) & 1;
    size_t base = ((((size_t)(k16 * 2 + 0) * 4 + grp) * 32 + l) * 8)
                  + (size_t)(ntp * 2 + reg) * 2 + (kr & 1);
    size_t lobase = base + (size_t)4 * 32 * 8;   // term stride
    g_Whf[base]   = __half_as_ushort(hh);
    g_Whf[lobase] = __half_as_ushort(hl);
}

// ---------------- kernel 2: Y = x @ W via mma.sync fp16 3-term ----------------
#define SMA_SZ 18432                 // 128 rows * 144B (36-float stride)
#define SMB_SZ 8192                  // per chunk: 2 k16 * 2 term * 4 grp * 32 * 16B
#define SM_TOTAL (2 * SMA_SZ + 2 * SMB_SZ)

__global__ void __launch_bounds__(128, 1) k_gemm(const float* __restrict__ x) {
    extern __shared__ char smem[];
    uint32_t sbA = (uint32_t)__cvta_generic_to_shared(smem);
    uint32_t sbB = sbA + 2 * SMA_SZ;

    int tid = threadIdx.x;
    int wid = tid >> 5, l = tid & 31;
    int mh = wid >> 1, nh = wid & 1;
    int m0 = blockIdx.x * TM;
    const float* xblk = x + (size_t)m0 * DK;
    const char* wsrc = (const char*)g_Whf;

    float4 C[4][4], S[4][4];
#pragma unroll
    for (int a = 0; a < 4; a++)
#pragma unroll
        for (int b = 0; b < 4; b++) {
            C[a][b] = make_float4(0.f, 0.f, 0.f, 0.f);
            S[a][b] = make_float4(0.f, 0.f, 0.f, 0.f);
        }

    int r_in = l >> 2;       // 0..7
    int cq   = l & 3;        // 0..3

    // ---- prologue: cp chunk 0
#pragma unroll
    for (int i = 0; i < 8; i++) {
        int idx = i * 128 + tid;
        int row = idx >> 3, q = idx & 7;
        cp_async16(sbA + (uint32_t)(row * 144 + q * 16),
                   xblk + (size_t)row * DK + q * 4);
    }
#pragma unroll
    for (int i = 0; i < 4; i++) {
        int idx = i * 128 + tid;
        cp_async16(sbB + (uint32_t)(idx * 16), wsrc + (size_t)idx * 16);
    }
    CP_COMMIT();

#pragma unroll 1
    for (int c = 0; c < NIT; c++) {
        int buf = c & 1;
        CP_WAIT0();
        __syncthreads();

        if (c + 1 < NIT) {
            int nb = (c + 1) & 1;
            int k0 = (c + 1) * KC;
            uint32_t aoff = sbA + (uint32_t)(nb * SMA_SZ);
            uint32_t boff = sbB + (uint32_t)(nb * SMB_SZ);
            const char* bs = wsrc + (size_t)(c + 1) * SMB_SZ;
#pragma unroll
            for (int i = 0; i < 8; i++) {
                int idx = i * 128 + tid;
                int row = idx >> 3, q = idx & 7;
                cp_async16(aoff + (uint32_t)(row * 144 + q * 16),
                           xblk + (size_t)row * DK + k0 + q * 4);
            }
#pragma unroll
            for (int i = 0; i < 4; i++) {
                int idx = i * 128 + tid;
                cp_async16(boff + (uint32_t)(idx * 16), bs + (size_t)idx * 16);
            }
            CP_COMMIT();
        }

        uint32_t ab = sbA + (uint32_t)(buf * SMA_SZ);
        uint32_t bb = sbB + (uint32_t)(buf * SMB_SZ);

#pragma unroll
        for (int ks = 0; ks < 2; ks++) {
            // B fragments: grp = nh*2 + g; 16B per lane = {nt0.b0, nt0.b1, nt1.b0, nt1.b1}
            uint4 BH[2], BL[2];
#pragma unroll
            for (int g = 0; g < 2; g++) {
                uint32_t bh = bb + (uint32_t)((((ks * 2 + 0) * 4 + nh * 2 + g) * 32 + l) * 16);
                uint32_t blo = bb + (uint32_t)((((ks * 2 + 1) * 4 + nh * 2 + g) * 32 + l) * 16);
                lds128(BH[g], bh);
                lds128(BL[g], blo);
            }

#pragma unroll
            for (int rt = 0; rt < 4; rt++) {
                int row = mh * 64 + rt * 16 + r_in;
                uint32_t ra = ab + (uint32_t)(row * 144 + (ks * 16 + cq * 2) * 4);
                float2 p0 = lds64f(ra);                       // (r, k..k+1)
                float2 p1 = lds64f(ra + 8 * 144);             // (r+8, k..k+1)
                float2 p2 = lds64f(ra + 32);                  // (r, k+8..k+9)
                float2 p3 = lds64f(ra + 8 * 144 + 32);        // (r+8, ...)

                uint32_t ah0, al0, ah1, al1, ah2, al2, ah3, al3;
                split_pair(p0, ah0, al0);
                split_pair(p1, ah1, al1);
                split_pair(p2, ah2, al2);
                split_pair(p3, ah3, al3);

                // nt0: BH[0].x/.y (b0,b1), nt1: BH[0].z/.w, nt2: BH[1].x/.y, nt3: BH[1].z/.w
                mma16(C[rt][0], ah0, ah1, ah2, ah3, BH[0].x, BH[0].y);
                mma16(C[rt][0], ah0, ah1, ah2, ah3, BL[0].x, BL[0].y);
                mma16(C[rt][0], al0, al1, al2, al3, BH[0].x, BH[0].y);

                mma16(C[rt][1], ah0, ah1, ah2, ah3, BH[0].z, BH[0].w);
                mma16(C[rt][1], ah0, ah1, ah2, ah3, BL[0].z, BL[0].w);
                mma16(C[rt][1], al0, al1, al2, al3, BH[0].z, BH[0].w);

                mma16(C[rt][2], ah0, ah1, ah2, ah3, BH[1].x, BH[1].y);
                mma16(C[rt][2], ah0, ah1, ah2, ah3, BL[1].x, BL[1].y);
                mma16(C[rt][2], al0, al1, al2, al3, BH[1].x, BH[1].y);

                mma16(C[rt][3], ah0, ah1, ah2, ah3, BH[1].z, BH[1].w);
                mma16(C[rt][3], ah0, ah1, ah2, ah3, BL[1].z, BL[1].w);
                mma16(C[rt][3], al0, al1, al2, al3, BH[1].z, BH[1].w);
            }
        }

        // drain every 16 chunks (shortens fp32 accumulation chain)
        if ((c & 15) == 15) {
#pragma unroll
            for (int a = 0; a < 4; a++)
#pragma unroll
                for (int b = 0; b < 4; b++) {
                    S[a][b].x += C[a][b].x; S[a][b].y += C[a][b].y;
                    S[a][b].z += C[a][b].z; S[a][b].w += C[a][b].w;
                    C[a][b] = make_float4(0.f, 0.f, 0.f, 0.f);
                }
        }
    }

    // ---- epilogue: un-scale (exact 2^-12), store Y, abs-max
    float mx = 0.0f;
#pragma unroll
    for (int rt = 0; rt < 4; rt++)
#pragma unroll
        for (int nt = 0; nt < 4; nt++) {
            float4 v = S[rt][nt];
            v.x *= WSCI; v.y *= WSCI; v.z *= WSCI; v.w *= WSCI;
            int row = m0 + mh * 64 + rt * 16 + r_in;
            int col = nh * 32 + nt * 8 + cq * 2;
            *(float2*)&g_Y[(size_t)row * NCOL + col]       = make_float2(v.x, v.y);
            *(float2*)&g_Y[(size_t)(row + 8) * NCOL + col] = make_float2(v.z, v.w);
            mx = fmaxf(mx, fmaxf(fmaxf(fabsf(v.x), fabsf(v.y)),
                                 fmaxf(fabsf(v.z), fabsf(v.w))));
        }
#pragma unroll
    for (int off = 16; off; off >>= 1)
        mx = fmaxf(mx, __shfl_xor_sync(0xffffffffu, mx, off));
    if (l == 0) atomicMax(&g_absmax_bits, __float_as_uint(mx));
}

// ---------------- kernel 3: NF4 quantize (midpoint count) ----------------
__global__ void k_quant(float* __restrict__ out, const float* __restrict__ qs, int n4) {
    const float L[16] = {
        -1.0f, -0.6961928009986877f, -0.5250730514526367f, -0.39491748809814453f,
        -0.28444138169288635f, -0.18477343022823334f, -0.09105003625154495f, 0.0f,
        0.07958029955625534f, 0.16093020141124725f, 0.24611230194568634f,
        0.33791524171829224f, 0.44070982933044434f, 0.5626170039176941f,
        0.7229568362236023f, 1.0f };
    float MID[15];
#pragma unroll
    for (int i = 0; i < 15; i++) MID[i] = 0.5f * (L[i] + L[i + 1]);

    int i = blockIdx.x * blockDim.x + threadIdx.x;
    if (i >= n4) return;
    float absmax = __uint_as_float(g_absmax_bits);
    float qscale = qs[0];
    float4 y = ((const float4*)g_Y)[i];
    float4 o;
    if (absmax > 0.0f) {
        float inv = 1.0f / absmax;
        float v[4] = { y.x * inv, y.y * inv, y.z * inv, y.w * inv };
        float r[4];
#pragma unroll
        for (int t = 0; t < 4; t++) {
            int idx = 0;
#pragma unroll
            for (int b = 0; b < 15; b++) idx += (v[t] > MID[b]) ? 1 : 0;
            r[t] = L[idx] * absmax;
        }
        o = make_float4(r[0], r[1], r[2], r[3]);
    } else {
        o = y;
    }
    o.x *= qscale; o.y *= qscale; o.z *= qscale; o.w *= qscale;
    ((float4*)out)[i] = o;
}

// ---------------- launch ----------------
extern "C" void kernel_launch(void* const* d_in, const int* in_sizes, int n_in,
                              void* d_out, int out_size) {
    const float* x  = (const float*)d_in[0];   // [4,4096,4096]
    const float* A  = (const float*)d_in[1];   // [64,64]
    const float* Bm = (const float*)d_in[2];   // [4096,64]
    const float* qs = (const float*)d_in[3];   // [1]
    const float* ri = (const float*)d_in[4];   // [64]
    float* out = (float*)d_out;

    int M = in_sizes[0] / DK;   // 16384

    cudaFuncSetAttribute(k_gemm, cudaFuncAttributeMaxDynamicSharedMemorySize, SM_TOTAL);

    k_prep<<<1, 64>>>(ri);
    k_w<<<DK / 4, dim3(64, 4)>>>(Bm, A);
    k_gemm<<<M / TM, 128, SM_TOTAL>>>(x);
    int n4 = (M * NCOL) / 4;
    k_quant<<<(n4 + 255) / 256, 256>>>(out, qs, n4);
}